// round 11
// baseline (speedup 1.0000x reference)
#include <cuda_runtime.h>

// ---------------- problem constants ----------------
#define NB    8
#define NH    8
#define NBH   64        // NB*NH
#define NT    4096      // tokens
#define DM    512       // model dim
#define DH    64        // head dim
#define ML    256       // landmarks
#define LG    16        // tokens per landmark group
#define NRT   32768     // NB*NT
#define QN    1536      // 3*NH*DH
#define KSPL  8         // split-K factor for big flash

#define LDS_S 136       // gemm engine A smem row stride
#define BS2   264       // bgemm2 B smem row stride (8*kq+cb conflict-free)
#define FPAD  68        // flash smem row stride

// ---------------- scratch (device globals; no allocation allowed) ----------------
__device__ float g_q [NBH * NT * DH];
__device__ float g_k [NBH * NT * DH];
__device__ float g_v [NBH * NT * DH];
__device__ float g_ql[NBH * ML * DH];
__device__ float g_kl[NBH * ML * DH];
__device__ float g_attn2 [NBH * ML * ML];
__device__ unsigned g_scalebits;          // max column-sum as float bits (positive)
__device__ float g_z0[NBH * ML * ML];
__device__ float g_z1[NBH * ML * ML];
__device__ float g_t1[NBH * ML * ML];
__device__ float g_t3[NBH * ML * ML];
__device__ float g_t5[NBH * ML * ML];
__device__ float g_out3[NBH * ML * DH];
__device__ float g_p   [NBH * ML * DH];
__device__ float g_oh  [NRT * DM];
__device__ float g_po[KSPL * NBH * ML * DH];   // split-K partial O (unnormalized)
__device__ float g_pm[KSPL * NBH * ML];        // split-K per-row max
__device__ float g_pl[KSPL * NBH * ML];        // split-K per-row l

__device__ __forceinline__ unsigned f2tf(float f) {
    unsigned r;
    asm("cvt.rna.tf32.f32 %0, %1;" : "=r"(r) : "f"(f));
    return r;
}

__device__ __forceinline__ void mma8(float c[4], const unsigned a[4],
                                     unsigned b0, unsigned b1) {
    asm volatile(
        "mma.sync.aligned.m16n8k8.row.col.f32.tf32.tf32.f32 "
        "{%0,%1,%2,%3}, {%4,%5,%6,%7}, {%8,%9}, {%0,%1,%2,%3};"
        : "+f"(c[0]), "+f"(c[1]), "+f"(c[2]), "+f"(c[3])
        : "r"(a[0]), "r"(a[1]), "r"(a[2]), "r"(a[3]), "r"(b0), "r"(b1));
}

// =====================================================================
// tf32 mma tile engine: 128x128 block tile, BK=16, 256 threads.
// (used by k_qkv / k_final, which already fill the machine)
// =====================================================================
__device__ __forceinline__ void gemm_tile_tf32(const float* __restrict__ Ag, int lda,
                                               const float* __restrict__ Bg, int ldb,
                                               int K,
                                               unsigned* sA, unsigned* sB,
                                               float acc[4][4][4]) {
    const int tid  = threadIdx.x;
    const int lane = tid & 31;
    const int wid  = tid >> 5;
    const int wr = (wid >> 2) * 64;
    const int wc = (wid & 3) * 32;

    const int a_row = tid & 127;
    const int a_kq  = tid >> 7;
    const int b_kr  = tid >> 5;
    const int b_n4  = tid & 31;

    const int nt = K >> 4;
    float4 ar0, ar1, br0, br1;
    ar0 = *(const float4*)&Ag[(size_t)a_row * lda + a_kq * 4];
    ar1 = *(const float4*)&Ag[(size_t)a_row * lda + (a_kq + 2) * 4];
    br0 = *(const float4*)&Bg[(size_t)b_kr * ldb + b_n4 * 4];
    br1 = *(const float4*)&Bg[(size_t)(b_kr + 8) * ldb + b_n4 * 4];

    {
        unsigned* As = sA;
        unsigned* Bs = sB;
        As[(a_kq * 4 + 0) * LDS_S + a_row] = f2tf(ar0.x);
        As[(a_kq * 4 + 1) * LDS_S + a_row] = f2tf(ar0.y);
        As[(a_kq * 4 + 2) * LDS_S + a_row] = f2tf(ar0.z);
        As[(a_kq * 4 + 3) * LDS_S + a_row] = f2tf(ar0.w);
        As[((a_kq + 2) * 4 + 0) * LDS_S + a_row] = f2tf(ar1.x);
        As[((a_kq + 2) * 4 + 1) * LDS_S + a_row] = f2tf(ar1.y);
        As[((a_kq + 2) * 4 + 2) * LDS_S + a_row] = f2tf(ar1.z);
        As[((a_kq + 2) * 4 + 3) * LDS_S + a_row] = f2tf(ar1.w);
        uint4 b0 = make_uint4(f2tf(br0.x), f2tf(br0.y), f2tf(br0.z), f2tf(br0.w));
        uint4 b1 = make_uint4(f2tf(br1.x), f2tf(br1.y), f2tf(br1.z), f2tf(br1.w));
        *(uint4*)&Bs[b_kr * LDS_S + b_n4 * 4]       = b0;
        *(uint4*)&Bs[(b_kr + 8) * LDS_S + b_n4 * 4] = b1;
    }
    __syncthreads();

    for (int t = 0; t < nt; ++t) {
        unsigned* As = sA + (t & 1) * (16 * LDS_S);
        unsigned* Bs = sB + (t & 1) * (16 * LDS_S);

        if (t + 1 < nt) {
            int k0 = (t + 1) * 16;
            ar0 = *(const float4*)&Ag[(size_t)a_row * lda + k0 + a_kq * 4];
            ar1 = *(const float4*)&Ag[(size_t)a_row * lda + k0 + (a_kq + 2) * 4];
            br0 = *(const float4*)&Bg[(size_t)(k0 + b_kr) * ldb + b_n4 * 4];
            br1 = *(const float4*)&Bg[(size_t)(k0 + b_kr + 8) * ldb + b_n4 * 4];
        }

#pragma unroll
        for (int kk = 0; kk < 16; kk += 8) {
            unsigned a[4][4], b[4][2];
            const int kr0 = kk + (lane & 3);
            const int kr1 = kk + (lane & 3) + 4;
#pragma unroll
            for (int ma = 0; ma < 4; ++ma) {
                int r = wr + ma * 16 + (lane >> 2);
                a[ma][0] = As[kr0 * LDS_S + r];
                a[ma][1] = As[kr0 * LDS_S + r + 8];
                a[ma][2] = As[kr1 * LDS_S + r];
                a[ma][3] = As[kr1 * LDS_S + r + 8];
            }
#pragma unroll
            for (int na = 0; na < 4; ++na) {
                int c = wc + na * 8 + (lane >> 2);
                b[na][0] = Bs[kr0 * LDS_S + c];
                b[na][1] = Bs[kr1 * LDS_S + c];
            }
#pragma unroll
            for (int ma = 0; ma < 4; ++ma)
#pragma unroll
                for (int na = 0; na < 4; ++na)
                    mma8(acc[ma][na], a[ma], b[na][0], b[na][1]);
        }

        if (t + 1 < nt) {
            unsigned* An = sA + ((t + 1) & 1) * (16 * LDS_S);
            unsigned* Bn = sB + ((t + 1) & 1) * (16 * LDS_S);
            An[(a_kq * 4 + 0) * LDS_S + a_row] = f2tf(ar0.x);
            An[(a_kq * 4 + 1) * LDS_S + a_row] = f2tf(ar0.y);
            An[(a_kq * 4 + 2) * LDS_S + a_row] = f2tf(ar0.z);
            An[(a_kq * 4 + 3) * LDS_S + a_row] = f2tf(ar0.w);
            An[((a_kq + 2) * 4 + 0) * LDS_S + a_row] = f2tf(ar1.x);
            An[((a_kq + 2) * 4 + 1) * LDS_S + a_row] = f2tf(ar1.y);
            An[((a_kq + 2) * 4 + 2) * LDS_S + a_row] = f2tf(ar1.z);
            An[((a_kq + 2) * 4 + 3) * LDS_S + a_row] = f2tf(ar1.w);
            uint4 b0 = make_uint4(f2tf(br0.x), f2tf(br0.y), f2tf(br0.z), f2tf(br0.w));
            uint4 b1 = make_uint4(f2tf(br1.x), f2tf(br1.y), f2tf(br1.z), f2tf(br1.w));
            *(uint4*)&Bn[b_kr * LDS_S + b_n4 * 4]       = b0;
            *(uint4*)&Bn[(b_kr + 8) * LDS_S + b_n4 * 4] = b1;
        }
        __syncthreads();
    }
}

// =====================================================================
// Kernel 1: qkv = x @ w_qkv, scatter to q/k/v head-major, scale q.
// =====================================================================
__global__ void __launch_bounds__(256) k_qkv(const float* __restrict__ X,
                                             const float* __restrict__ W) {
    __shared__ unsigned sA[2 * 16 * LDS_S];
    __shared__ unsigned sB[2 * 16 * LDS_S];
    const int colbase = blockIdx.x * 128;
    const int rowbase = blockIdx.y * 128;
    float acc[4][4][4];
#pragma unroll
    for (int i = 0; i < 4; ++i)
#pragma unroll
        for (int j = 0; j < 4; ++j)
#pragma unroll
            for (int u = 0; u < 4; ++u) acc[i][j][u] = 0.f;

    gemm_tile_tf32(X + (size_t)rowbase * DM, DM, W + colbase, QN, DM, sA, sB, acc);

    const int lane = threadIdx.x & 31, wid = threadIdx.x >> 5;
    const int wr = (wid >> 2) * 64, wc = (wid & 3) * 32;
#pragma unroll
    for (int ma = 0; ma < 4; ++ma) {
#pragma unroll
        for (int na = 0; na < 4; ++na) {
            int r0 = rowbase + wr + ma * 16 + (lane >> 2);
            int c  = colbase + wc + na * 8 + (lane & 3) * 2;
            int part = c >> 9, rem = c & 511;
            int h = rem >> 6, d = rem & 63;
#pragma unroll
            for (int half = 0; half < 2; ++half) {
                int r = r0 + half * 8;
                int bb = r >> 12, n = r & 4095;
                size_t dst = (((size_t)(bb * 8 + h)) * NT + n) * DH + d;
                float v0 = acc[ma][na][half * 2 + 0];
                float v1 = acc[ma][na][half * 2 + 1];
                if (part == 0)      *(float2*)&g_q[dst] = make_float2(v0 * 0.125f, v1 * 0.125f);
                else if (part == 1) *(float2*)&g_k[dst] = make_float2(v0, v1);
                else                *(float2*)&g_v[dst] = make_float2(v0, v1);
            }
        }
    }
}

// =====================================================================
// Kernel 7: batched GEMM for pinv, 128x256 CTA tile, grid (NBH, 2)
// = 128 CTAs = one full wave. C = alpha*(A@B) + beta*E.
// Warp grid 2x4, warp tile 64x64 (4x8 m16n8k8 atoms).
// =====================================================================
__global__ void __launch_bounds__(256) k_bgemm2(const float* __restrict__ A,
                                                const float* __restrict__ B,
                                                const float* __restrict__ E,
                                                float* __restrict__ C,
                                                float alpha, float beta) {
    extern __shared__ unsigned dsm[];
    unsigned* sA = dsm;                       // 2 * 16 * LDS_S
    unsigned* sB = dsm + 2 * 16 * LDS_S;      // 2 * 16 * BS2
    const int tid = threadIdx.x;
    const int lane = tid & 31, w = tid >> 5;
    const int wr = (w >> 2) * 64;             // 0 / 64
    const int wc = (w & 3) * 64;              // 0 / 64 / 128 / 192
    const size_t base = (size_t)blockIdx.x * (ML * ML);
    const int rowbase = blockIdx.y * 128;
    const float* Ag = A + base + (size_t)rowbase * ML;
    const float* Bg = B + base;

    const int a_row = tid & 127;
    const int a_kq  = tid >> 7;
    const int b_kr  = tid >> 4;               // 0..15
    const int b_c0  = (tid & 15) * 16;        // 0..240

    float acc[4][8][4];
#pragma unroll
    for (int i = 0; i < 4; ++i)
#pragma unroll
        for (int j = 0; j < 8; ++j)
#pragma unroll
            for (int u = 0; u < 4; ++u) acc[i][j][u] = 0.f;

    float4 ar0, ar1, bv[4];
    ar0 = *(const float4*)&Ag[(size_t)a_row * ML + a_kq * 4];
    ar1 = *(const float4*)&Ag[(size_t)a_row * ML + (a_kq + 2) * 4];
#pragma unroll
    for (int i = 0; i < 4; ++i)
        bv[i] = *(const float4*)&Bg[(size_t)b_kr * ML + b_c0 + 4 * i];

    // stage tile 0
    {
        unsigned* As = sA;
        unsigned* Bs = sB;
        As[(a_kq * 4 + 0) * LDS_S + a_row] = f2tf(ar0.x);
        As[(a_kq * 4 + 1) * LDS_S + a_row] = f2tf(ar0.y);
        As[(a_kq * 4 + 2) * LDS_S + a_row] = f2tf(ar0.z);
        As[(a_kq * 4 + 3) * LDS_S + a_row] = f2tf(ar0.w);
        As[((a_kq + 2) * 4 + 0) * LDS_S + a_row] = f2tf(ar1.x);
        As[((a_kq + 2) * 4 + 1) * LDS_S + a_row] = f2tf(ar1.y);
        As[((a_kq + 2) * 4 + 2) * LDS_S + a_row] = f2tf(ar1.z);
        As[((a_kq + 2) * 4 + 3) * LDS_S + a_row] = f2tf(ar1.w);
#pragma unroll
        for (int i = 0; i < 4; ++i) {
            uint4 bt = make_uint4(f2tf(bv[i].x), f2tf(bv[i].y), f2tf(bv[i].z), f2tf(bv[i].w));
            *(uint4*)&Bs[b_kr * BS2 + b_c0 + 4 * i] = bt;
        }
    }
    __syncthreads();

    for (int t = 0; t < 16; ++t) {
        unsigned* As = sA + (t & 1) * (16 * LDS_S);
        unsigned* Bs = sB + (t & 1) * (16 * BS2);

        if (t + 1 < 16) {
            int k0 = (t + 1) * 16;
            ar0 = *(const float4*)&Ag[(size_t)a_row * ML + k0 + a_kq * 4];
            ar1 = *(const float4*)&Ag[(size_t)a_row * ML + k0 + (a_kq + 2) * 4];
#pragma unroll
            for (int i = 0; i < 4; ++i)
                bv[i] = *(const float4*)&Bg[(size_t)(k0 + b_kr) * ML + b_c0 + 4 * i];
        }

#pragma unroll
        for (int kk = 0; kk < 16; kk += 8) {
            unsigned a[4][4], b[8][2];
            const int kr0 = kk + (lane & 3);
            const int kr1 = kk + (lane & 3) + 4;
#pragma unroll
            for (int ma = 0; ma < 4; ++ma) {
                int r = wr + ma * 16 + (lane >> 2);
                a[ma][0] = As[kr0 * LDS_S + r];
                a[ma][1] = As[kr0 * LDS_S + r + 8];
                a[ma][2] = As[kr1 * LDS_S + r];
                a[ma][3] = As[kr1 * LDS_S + r + 8];
            }
#pragma unroll
            for (int na = 0; na < 8; ++na) {
                int c = wc + na * 8 + (lane >> 2);
                b[na][0] = Bs[kr0 * BS2 + c];
                b[na][1] = Bs[kr1 * BS2 + c];
            }
#pragma unroll
            for (int ma = 0; ma < 4; ++ma)
#pragma unroll
                for (int na = 0; na < 8; ++na)
                    mma8(acc[ma][na], a[ma], b[na][0], b[na][1]);
        }

        if (t + 1 < 16) {
            unsigned* An = sA + ((t + 1) & 1) * (16 * LDS_S);
            unsigned* Bn = sB + ((t + 1) & 1) * (16 * BS2);
            An[(a_kq * 4 + 0) * LDS_S + a_row] = f2tf(ar0.x);
            An[(a_kq * 4 + 1) * LDS_S + a_row] = f2tf(ar0.y);
            An[(a_kq * 4 + 2) * LDS_S + a_row] = f2tf(ar0.z);
            An[(a_kq * 4 + 3) * LDS_S + a_row] = f2tf(ar0.w);
            An[((a_kq + 2) * 4 + 0) * LDS_S + a_row] = f2tf(ar1.x);
            An[((a_kq + 2) * 4 + 1) * LDS_S + a_row] = f2tf(ar1.y);
            An[((a_kq + 2) * 4 + 2) * LDS_S + a_row] = f2tf(ar1.z);
            An[((a_kq + 2) * 4 + 3) * LDS_S + a_row] = f2tf(ar1.w);
#pragma unroll
            for (int i = 0; i < 4; ++i) {
                uint4 bt = make_uint4(f2tf(bv[i].x), f2tf(bv[i].y), f2tf(bv[i].z), f2tf(bv[i].w));
                *(uint4*)&Bn[b_kr * BS2 + b_c0 + 4 * i] = bt;
            }
        }
        __syncthreads();
    }

#pragma unroll
    for (int ma = 0; ma < 4; ++ma) {
#pragma unroll
        for (int na = 0; na < 8; ++na) {
            int r0 = rowbase + wr + ma * 16 + (lane >> 2);
            int c  = wc + na * 8 + (lane & 3) * 2;
            size_t i0 = base + (size_t)r0 * ML + c;
            size_t i1 = i0 + 8 * ML;
            float2 e0 = make_float2(0.f, 0.f), e1 = make_float2(0.f, 0.f);
            if (beta != 0.f) { e0 = *(const float2*)&E[i0]; e1 = *(const float2*)&E[i1]; }
            float2 o0 = make_float2(alpha * acc[ma][na][0] + beta * e0.x,
                                    alpha * acc[ma][na][1] + beta * e0.y);
            float2 o1 = make_float2(alpha * acc[ma][na][2] + beta * e1.x,
                                    alpha * acc[ma][na][3] + beta * e1.y);
            *(float2*)&C[i0] = o0;
            *(float2*)&C[i1] = o1;
        }
    }
}

// =====================================================================
// Kernel 10: Y = oh @ w_out + b_out
// =====================================================================
__global__ void __launch_bounds__(256) k_final(const float* __restrict__ W,
                                               const float* __restrict__ bias,
                                               float* __restrict__ Y) {
    __shared__ unsigned sA[2 * 16 * LDS_S];
    __shared__ unsigned sB[2 * 16 * LDS_S];
    const int colbase = blockIdx.x * 128;
    const int rowbase = blockIdx.y * 128;
    float acc[4][4][4];
#pragma unroll
    for (int i = 0; i < 4; ++i)
#pragma unroll
        for (int j = 0; j < 4; ++j)
#pragma unroll
            for (int u = 0; u < 4; ++u) acc[i][j][u] = 0.f;

    gemm_tile_tf32(g_oh + (size_t)rowbase * DM, DM, W + colbase, DM, DM, sA, sB, acc);

    const int lane = threadIdx.x & 31, wid = threadIdx.x >> 5;
    const int wr = (wid >> 2) * 64, wc = (wid & 3) * 32;
#pragma unroll
    for (int ma = 0; ma < 4; ++ma) {
#pragma unroll
        for (int na = 0; na < 4; ++na) {
            int r0 = rowbase + wr + ma * 16 + (lane >> 2);
            int c  = colbase + wc + na * 8 + (lane & 3) * 2;
            float2 bb = *(const float2*)&bias[c];
            float2 o0 = make_float2(acc[ma][na][0] + bb.x, acc[ma][na][1] + bb.y);
            float2 o1 = make_float2(acc[ma][na][2] + bb.x, acc[ma][na][3] + bb.y);
            *(float2*)&Y[(size_t)r0 * DM + c] = o0;
            *(float2*)&Y[(size_t)(r0 + 8) * DM + c] = o1;
        }
    }
}

// =====================================================================
// Kernel 2: landmarks = mean over groups of 16 tokens.
// =====================================================================
__global__ void k_landmark() {
    const int blk = blockIdx.x;
    const int bh = blk >> 8, m = blk & 255;
    const int d = threadIdx.x;
    const float* qb = g_q + ((size_t)bh * NT + m * LG) * DH + d;
    const float* kb = g_k + ((size_t)bh * NT + m * LG) * DH + d;
    float sq = 0.f, sk = 0.f;
#pragma unroll
    for (int t = 0; t < LG; ++t) { sq += qb[t * DH]; sk += kb[t * DH]; }
    g_ql[((size_t)bh * ML + m) * DH + d] = sq * (1.f / LG);
    g_kl[((size_t)bh * ML + m) * DH + d] = sk * (1.f / LG);
}

// =====================================================================
// Kernel 3: attn2 = softmax(ql @ kl^T) rows. Also resets g_scalebits.
// =====================================================================
__global__ void __launch_bounds__(256) k_attn2() {
    extern __shared__ float sm[];
    float* qls   = sm;
    float* kls   = sm + 64 * 68;
    float* sc    = kls + 256 * 68;
    float* rowiv = sc + 64 * 256;
    const int bh = blockIdx.x, chunk = blockIdx.y, tid = threadIdx.x;

    if (bh == 0 && chunk == 0 && tid == 0) g_scalebits = 0u;

    const float* klb = g_kl + (size_t)bh * ML * DH;
    for (int i = tid; i < 256 * 16; i += 256) {
        int row = i >> 4, c4 = (i & 15) * 4;
        *(float4*)&kls[row * 68 + c4] = *(const float4*)&klb[row * DH + c4];
    }
    const float* qlb = g_ql + ((size_t)bh * ML + chunk * 64) * DH;
    for (int i = tid; i < 64 * 16; i += 256) {
        int row = i >> 4, c4 = (i & 15) * 4;
        *(float4*)&qls[row * 68 + c4] = *(const float4*)&qlb[row * DH + c4];
    }
    __syncthreads();

    const int r = tid >> 2, cg = tid & 3;
    float4 qreg[16];
#pragma unroll
    for (int u = 0; u < 16; ++u) qreg[u] = *(const float4*)&qls[r * 68 + u * 4];

    float mloc = -1e30f;
    for (int ci = 0; ci < 64; ++ci) {
        int c = ci * 4 + cg;
        const float4* kv = (const float4*)&kls[c * 68];
        float s = 0.f;
#pragma unroll
        for (int u = 0; u < 16; ++u) {
            float4 k4 = kv[u];
            s += qreg[u].x * k4.x + qreg[u].y * k4.y + qreg[u].z * k4.z + qreg[u].w * k4.w;
        }
        sc[r * 256 + c] = s;
        mloc = fmaxf(mloc, s);
    }
    mloc = fmaxf(mloc, __shfl_xor_sync(0xFFFFFFFFu, mloc, 1));
    mloc = fmaxf(mloc, __shfl_xor_sync(0xFFFFFFFFu, mloc, 2));
    float ssum = 0.f;
    for (int ci = 0; ci < 64; ++ci) {
        int c = ci * 4 + cg;
        float p = __expf(sc[r * 256 + c] - mloc);
        sc[r * 256 + c] = p;
        ssum += p;
    }
    ssum += __shfl_xor_sync(0xFFFFFFFFu, ssum, 1);
    ssum += __shfl_xor_sync(0xFFFFFFFFu, ssum, 2);
    if (cg == 0) rowiv[r] = 1.f / ssum;
    __syncthreads();

    float* dst = g_attn2 + (size_t)bh * (ML * ML) + (size_t)chunk * 64 * 256;
    for (int i = tid; i < 64 * 256; i += 256)
        dst[i] = sc[i] * rowiv[i >> 8];
}

// =====================================================================
// Kernel 4: column sums + fused global max (atomicMax on positive-float bits).
// =====================================================================
__global__ void k_colsum() {
    __shared__ float red[256];
    const int bh = blockIdx.x, j = threadIdx.x;
    const float* a = g_attn2 + (size_t)bh * (ML * ML);
    float s = 0.f;
    for (int i = 0; i < ML; ++i) s += a[i * ML + j];
    red[j] = s;
    __syncthreads();
    for (int st = 128; st > 0; st >>= 1) {
        if (j < st) red[j] = fmaxf(red[j], red[j + st]);
        __syncthreads();
    }
    if (j == 0) atomicMax(&g_scalebits, __float_as_uint(red[0]));
}

__global__ void k_zinit() {
    const int bh = blockIdx.x;
    const float scl = 1.f / __uint_as_float(g_scalebits);
    float* z = g_z0 + (size_t)bh * (ML * ML);
    const float* a = g_attn2 + (size_t)bh * (ML * ML);
    for (int idx = threadIdx.x; idx < ML * ML; idx += 256) {
        int i = idx >> 8, j = idx & 255;
        z[idx] = a[j * ML + i] * scl;
    }
}

// =====================================================================
// Flash core (tensor-core, 64 q rows, 64-key tiles).
// =====================================================================
template<int PART>
__device__ __forceinline__ void flash_body(const float* __restrict__ Q,
                                           const float* __restrict__ K,
                                           const float* __restrict__ V,
                                           float* __restrict__ Out,
                                           int nkeys_total, int ntiles, int ktile0,
                                           int mode) {
    extern __shared__ float sm[];
    float*    Ts = sm;
    float*    Vs = sm + 64 * FPAD;
    float*    Ss = sm + 2 * 64 * FPAD;
    float*    sf = sm + 3 * 64 * FPAD;
    float*    sl = sf + 64;
    unsigned* Tu = (unsigned*)Ts;
    unsigned* Vu = (unsigned*)Vs;
    unsigned* Su = (unsigned*)Ss;

    const int tid = threadIdx.x;
    const int lane = tid & 31, w = tid >> 5;
    const int wrow = (w >> 1) * 16;
    const int wcol = (w & 1) * 32;
    const int bh = blockIdx.x, chunk = blockIdx.y;
    const int nq = (int)gridDim.y * 64;

    const float* Qb = Q + ((size_t)bh * nq + chunk * 64) * DH;
    const float* Kb = K + (size_t)bh * nkeys_total * DH;
    const float* Vb = V + (size_t)bh * nkeys_total * DH;

    const int strow = tid & 63;
    const int stc0  = (tid >> 6) * 16;

#pragma unroll
    for (int i = 0; i < 4; ++i) {
        float4 qv = *(const float4*)&Qb[strow * DH + stc0 + 4 * i];
        Tu[(stc0 + 4*i + 0) * FPAD + strow] = f2tf(qv.x);
        Tu[(stc0 + 4*i + 1) * FPAD + strow] = f2tf(qv.y);
        Tu[(stc0 + 4*i + 2) * FPAD + strow] = f2tf(qv.z);
        Tu[(stc0 + 4*i + 3) * FPAD + strow] = f2tf(qv.w);
    }
    __syncthreads();

    unsigned qf[8][4];
    {
        const int r = wrow + (lane >> 2);
        const int kq = lane & 3;
#pragma unroll
        for (int ka = 0; ka < 8; ++ka) {
            qf[ka][0] = Tu[(8*ka + kq) * FPAD + r];
            qf[ka][1] = Tu[(8*ka + kq) * FPAD + r + 8];
            qf[ka][2] = Tu[(8*ka + kq + 4) * FPAD + r];
            qf[ka][3] = Tu[(8*ka + kq + 4) * FPAD + r + 8];
        }
    }
    __syncthreads();

    float oacc[4][4];
#pragma unroll
    for (int na = 0; na < 4; ++na)
#pragma unroll
        for (int u = 0; u < 4; ++u) oacc[na][u] = 0.f;
    float mrow = -1e30f, lrow = 0.f;
    const int srow = tid >> 2, scg = tid & 3;

    for (int kt = ktile0; kt < ktile0 + ntiles; ++kt) {
        {
            const float* Kt_ = Kb + (size_t)kt * 64 * DH;
            const float* Vt_ = Vb + (size_t)kt * 64 * DH;
#pragma unroll
            for (int i = 0; i < 4; ++i) {
                float4 kv = *(const float4*)&Kt_[strow * DH + stc0 + 4 * i];
                Tu[(stc0 + 4*i + 0) * FPAD + strow] = f2tf(kv.x);
                Tu[(stc0 + 4*i + 1) * FPAD + strow] = f2tf(kv.y);
                Tu[(stc0 + 4*i + 2) * FPAD + strow] = f2tf(kv.z);
                Tu[(stc0 + 4*i + 3) * FPAD + strow] = f2tf(kv.w);
                float4 vv = *(const float4*)&Vt_[strow * DH + stc0 + 4 * i];
                uint4 vt = make_uint4(f2tf(vv.x), f2tf(vv.y), f2tf(vv.z), f2tf(vv.w));
                *(uint4*)&Vu[strow * FPAD + stc0 + 4 * i] = vt;
            }
        }
        __syncthreads();

        float sacc[4][4];
#pragma unroll
        for (int na = 0; na < 4; ++na)
#pragma unroll
            for (int u = 0; u < 4; ++u) sacc[na][u] = 0.f;
        {
            const int kq = lane & 3, cb = lane >> 2;
#pragma unroll
            for (int ka = 0; ka < 8; ++ka) {
                unsigned b[4][2];
#pragma unroll
                for (int na = 0; na < 4; ++na) {
                    int c = wcol + na * 8 + cb;
                    b[na][0] = Tu[(8*ka + kq) * FPAD + c];
                    b[na][1] = Tu[(8*ka + kq + 4) * FPAD + c];
                }
#pragma unroll
                for (int na = 0; na < 4; ++na)
                    mma8(sacc[na], qf[ka], b[na][0], b[na][1]);
            }
        }
        {
            const int r = wrow + (lane >> 2), c = wcol + 2 * (lane & 3);
#pragma unroll
            for (int na = 0; na < 4; ++na) {
                *(float2*)&Ss[r * FPAD + c + na*8]       = make_float2(sacc[na][0], sacc[na][1]);
                *(float2*)&Ss[(r + 8) * FPAD + c + na*8] = make_float2(sacc[na][2], sacc[na][3]);
            }
        }
        __syncthreads();

        {
            float sv[16];
#pragma unroll
            for (int i = 0; i < 16; i += 4) {
                float4 s4 = *(const float4*)&Ss[srow * FPAD + scg * 16 + i];
                sv[i] = s4.x; sv[i+1] = s4.y; sv[i+2] = s4.z; sv[i+3] = s4.w;
            }
            float tmax = -1e30f;
#pragma unroll
            for (int i = 0; i < 16; ++i) tmax = fmaxf(tmax, sv[i]);
            tmax = fmaxf(tmax, __shfl_xor_sync(0xFFFFFFFFu, tmax, 1));
            tmax = fmaxf(tmax, __shfl_xor_sync(0xFFFFFFFFu, tmax, 2));
            float mnew = fmaxf(mrow, tmax);
            float factor = __expf(mrow - mnew);
            float psum = 0.f;
#pragma unroll
            for (int i = 0; i < 16; ++i) { float p = __expf(sv[i] - mnew); psum += p; sv[i] = p; }
#pragma unroll
            for (int i = 0; i < 16; i += 4) {
                uint4 pu = make_uint4(f2tf(sv[i]), f2tf(sv[i+1]), f2tf(sv[i+2]), f2tf(sv[i+3]));
                *(uint4*)&Su[srow * FPAD + scg * 16 + i] = pu;
            }
            psum += __shfl_xor_sync(0xFFFFFFFFu, psum, 1);
            psum += __shfl_xor_sync(0xFFFFFFFFu, psum, 2);
            lrow = lrow * factor + psum;
            mrow = mnew;
            if (scg == 0) sf[srow] = factor;
        }
        __syncthreads();

        {
            const int r = wrow + (lane >> 2);
            const float f0 = sf[r], f1 = sf[r + 8];
#pragma unroll
            for (int na = 0; na < 4; ++na) {
                oacc[na][0] *= f0; oacc[na][1] *= f0;
                oacc[na][2] *= f1; oacc[na][3] *= f1;
            }
            const int kq = lane & 3, cb = lane >> 2;
#pragma unroll
            for (int ka = 0; ka < 8; ++ka) {
                unsigned a[4];
                a[0] = Su[r * FPAD + 8*ka + kq];
                a[1] = Su[(r + 8) * FPAD + 8*ka + kq];
                a[2] = Su[r * FPAD + 8*ka + kq + 4];
                a[3] = Su[(r + 8) * FPAD + 8*ka + kq + 4];
                unsigned b[4][2];
#pragma unroll
                for (int na = 0; na < 4; ++na) {
                    int c = wcol + na * 8 + cb;
                    b[na][0] = Vu[(8*ka + kq) * FPAD + c];
                    b[na][1] = Vu[(8*ka + kq + 4) * FPAD + c];
                }
#pragma unroll
                for (int na = 0; na < 4; ++na)
                    mma8(oacc[na], a, b[na][0], b[na][1]);
            }
        }
        __syncthreads();
    }

    if (PART) {
        const int s = blockIdx.z;
        const int r = wrow + (lane >> 2), c = wcol + 2 * (lane & 3);
        const int g0 = chunk * 64 + r;
        float* po = g_po + ((size_t)(s * NBH + bh) * ML) * DH;
#pragma unroll
        for (int na = 0; na < 4; ++na) {
            *(float2*)&po[(size_t)g0 * DH + c + na*8] =
                make_float2(oacc[na][0], oacc[na][1]);
            *(float2*)&po[(size_t)(g0 + 8) * DH + c + na*8] =
                make_float2(oacc[na][2], oacc[na][3]);
        }
        if (scg == 0) {
            size_t mi = (size_t)(s * NBH + bh) * ML + chunk * 64 + srow;
            g_pm[mi] = mrow;
            g_pl[mi] = lrow;
        }
    } else {
        if (scg == 0) sl[srow] = lrow;
        __syncthreads();
        const int r = wrow + (lane >> 2), c = wcol + 2 * (lane & 3);
        const float i0 = 1.f / sl[r], i1 = 1.f / sl[r + 8];
        size_t obase; int ostride;
        if (mode == 0) { obase = (size_t)bh * nq * DH; ostride = DH; }
        else {
            int b_ = bh >> 3, h = bh & 7;
            obase = (size_t)b_ * NT * DM + h * DH;
            ostride = DM;
        }
        const int g0 = chunk * 64 + r;
#pragma unroll
        for (int na = 0; na < 4; ++na) {
            *(float2*)&Out[obase + (size_t)g0 * ostride + c + na*8] =
                make_float2(oacc[na][0] * i0, oacc[na][1] * i0);
            *(float2*)&Out[obase + (size_t)(g0 + 8) * ostride + c + na*8] =
                make_float2(oacc[na][2] * i1, oacc[na][3] * i1);
        }
    }
}

__global__ void __launch_bounds__(256) k_flash(const float* __restrict__ Q,
                                               const float* __restrict__ K,
                                               const float* __restrict__ V,
                                               float* __restrict__ Out,
                                               int nkeys, int mode) {
    flash_body<0>(Q, K, V, Out, nkeys, nkeys >> 6, 0, mode);
}

__global__ void __launch_bounds__(256) k_flash_part(const float* __restrict__ Q,
                                                    const float* __restrict__ K,
                                                    const float* __restrict__ V) {
    const int s = blockIdx.z;
    flash_body<1>(Q, K, V, nullptr, NT, (NT / KSPL) >> 6, s * ((NT / KSPL) >> 6), 0);
}

// combine: out3 = sum_s po_s * exp(m_s - gm) / sum_s l_s * exp(m_s - gm)
__global__ void __launch_bounds__(256) k_combine() {
    const int bh = blockIdx.x, chunk = blockIdx.y, tid = threadIdx.x;
    const int q = chunk * 64 + (tid >> 2);
    const int d0 = (tid & 3) * 16;

    float m[KSPL], l[KSPL];
    float gm = -1e30f;
#pragma unroll
    for (int s = 0; s < KSPL; ++s) {
        size_t mi = (size_t)(s * NBH + bh) * ML + q;
        m[s] = g_pm[mi];
        l[s] = g_pl[mi];
        gm = fmaxf(gm, m[s]);
    }
    float L = 0.f;
    float wgt[KSPL];
#pragma unroll
    for (int s = 0; s < KSPL; ++s) {
        wgt[s] = __expf(m[s] - gm);
        L += l[s] * wgt[s];
    }
    float4 o[4];
#pragma unroll
    for (int u = 0; u < 4; ++u) o[u] = make_float4(0.f, 0.f, 0.f, 0.f);
#pragma unroll
    for (int s = 0; s < KSPL; ++s) {
        const float* po = g_po + (((size_t)(s * NBH + bh) * ML + q)) * DH + d0;
        float ws = wgt[s];
#pragma unroll
        for (int u = 0; u < 4; ++u) {
            float4 pv = *(const float4*)&po[u * 4];
            o[u].x = fmaf(ws, pv.x, o[u].x);
            o[u].y = fmaf(ws, pv.y, o[u].y);
            o[u].z = fmaf(ws, pv.z, o[u].z);
            o[u].w = fmaf(ws, pv.w, o[u].w);
        }
    }
    float inv = 1.f / L;
    float* dst = g_out3 + ((size_t)bh * ML + q) * DH + d0;
#pragma unroll
    for (int u = 0; u < 4; ++u) {
        *(float4*)&dst[u * 4] = make_float4(o[u].x * inv, o[u].y * inv,
                                            o[u].z * inv, o[u].w * inv);
    }
}

// =====================================================================
// Kernel 9: p = z @ out3  ([256,256]@[256,64] per bh)
// =====================================================================
__global__ void __launch_bounds__(256) k_pmat(const float* __restrict__ Z) {
    extern __shared__ float sm[];
    const int bh = blockIdx.x, tid = threadIdx.x;
    const float* o3 = g_out3 + (size_t)bh * ML * DH;
    for (int i = tid; i < ML * 16; i += 256)
        ((float4*)sm)[i] = ((const float4*)o3)[i];
    __syncthreads();

    const float* zrow = Z + ((size_t)bh * ML + tid) * ML;
    float4 acc[16];
#pragma unroll
    for (int u = 0; u < 16; ++u) acc[u] = make_float4(0.f, 0.f, 0.f, 0.f);
    for (int j = 0; j < ML; ++j) {
        float zij = zrow[j];
        const float4* vr = (const float4*)&sm[j * DH];
#pragma unroll
        for (int u = 0; u < 16; ++u) {
            float4 v = vr[u];
            acc[u].x = fmaf(zij, v.x, acc[u].x);
            acc[u].y = fmaf(zij, v.y, acc[u].y);
            acc[u].z = fmaf(zij, v.z, acc[u].z);
            acc[u].w = fmaf(zij, v.w, acc[u].w);
        }
    }
    float4* dst = (float4*)(g_p + ((size_t)bh * ML + tid) * DH);
#pragma unroll
    for (int u = 0; u < 16; ++u) dst[u] = acc[u];
}

// =====================================================================
// Host launcher
// =====================================================================
extern "C" void kernel_launch(void* const* d_in, const int* in_sizes, int n_in,
                              void* d_out, int out_size) {
    (void)in_sizes; (void)n_in; (void)out_size;
    const float* x     = (const float*)d_in[0];
    const float* w_qkv = (const float*)d_in[1];
    const float* w_out = (const float*)d_in[2];
    const float* b_out = (const float*)d_in[3];
    float* out = (float*)d_out;

    const int FLASH_SMEM = (3 * 64 * FPAD + 128) * 4;
    const int ATTN2_SMEM = (64*68 + 256*68 + 64*256 + 64) * 4;
    const int PMAT_SMEM  = ML * DH * 4;
    const int BG2_SMEM   = (2 * 16 * LDS_S + 2 * 16 * BS2) * 4;   // 51200
    cudaFuncSetAttribute(k_flash, cudaFuncAttributeMaxDynamicSharedMemorySize, FLASH_SMEM);
    cudaFuncSetAttribute(k_flash_part, cudaFuncAttributeMaxDynamicSharedMemorySize, FLASH_SMEM);
    cudaFuncSetAttribute(k_attn2, cudaFuncAttributeMaxDynamicSharedMemorySize, ATTN2_SMEM);
    cudaFuncSetAttribute(k_pmat,  cudaFuncAttributeMaxDynamicSharedMemorySize, PMAT_SMEM);
    cudaFuncSetAttribute(k_bgemm2, cudaFuncAttributeMaxDynamicSharedMemorySize, BG2_SMEM);

    float *z0, *z1, *t1, *t3, *t5, *a2, *ql, *kl, *kp, *vp, *qp, *pp, *oh;
    cudaGetSymbolAddress((void**)&z0, g_z0);
    cudaGetSymbolAddress((void**)&z1, g_z1);
    cudaGetSymbolAddress((void**)&t1, g_t1);
    cudaGetSymbolAddress((void**)&t3, g_t3);
    cudaGetSymbolAddress((void**)&t5, g_t5);
    cudaGetSymbolAddress((void**)&a2, g_attn2);
    cudaGetSymbolAddress((void**)&ql, g_ql);
    cudaGetSymbolAddress((void**)&kl, g_kl);
    cudaGetSymbolAddress((void**)&kp, g_k);
    cudaGetSymbolAddress((void**)&vp, g_v);
    cudaGetSymbolAddress((void**)&qp, g_q);
    cudaGetSymbolAddress((void**)&pp, g_p);
    cudaGetSymbolAddress((void**)&oh, g_oh);

    // 1. projections + head scatter (tf32 mma)
    k_qkv<<<dim3(12, 256), 256>>>(x, w_qkv);
    // 2. landmarks
    k_landmark<<<NBH * ML, DH>>>();
    // 3. attn2 (softmaxed); resets g_scalebits
    k_attn2<<<dim3(NBH, 4), 256, ATTN2_SMEM>>>();
    // 4. out3 partials = flash(ql, k, v) over 4096 keys, split-K x8
    //    (position 4 so ncu's profiled launch catches it)
    k_flash_part<<<dim3(NBH, 4, KSPL), 256, FLASH_SMEM>>>(ql, kp, vp);
    k_combine<<<dim3(NBH, 4), 256>>>();
    // 5. pinv init: colsum/max + z0
    k_colsum<<<NBH, ML>>>();
    k_zinit<<<NBH, 256>>>();
    // 6. Moore-Penrose iterations (wide-tile single-wave GEMMs)
    float* zc = z0; float* zn = z1;
    for (int it = 0; it < 6; ++it) {
        k_bgemm2<<<dim3(NBH, 2), 256, BG2_SMEM>>>(a2, zc, a2, t1,  1.f,   0.f);
        k_bgemm2<<<dim3(NBH, 2), 256, BG2_SMEM>>>(t1, t1, t1, t3, -1.f,   7.f);
        k_bgemm2<<<dim3(NBH, 2), 256, BG2_SMEM>>>(t1, t3, t1, t5, -1.f,  15.f);
        k_bgemm2<<<dim3(NBH, 2), 256, BG2_SMEM>>>(zc, t5, zc, zn, -0.25f, 3.25f);
        float* tmp = zc; zc = zn; zn = tmp;
    }
    // 7. p = attn2_inv @ out3
    k_pmat<<<NBH, 256, PMAT_SMEM>>>(zc);
    // 8. oh = softmax(q@kl^T) @ p  (tensor-core flash over 256 keys)
    k_flash<<<dim3(NBH, 64), 256, FLASH_SMEM>>>(qp, kl, pp, oh, ML, 1);
    // 9. final projection + bias (tf32 mma)
    k_final<<<dim3(4, 256), 256>>>(w_out, b_out, out);
}

// round 12
// speedup vs baseline: 1.1476x; 1.1476x over previous
#include <cuda_runtime.h>

// ---------------- problem constants ----------------
#define NB    8
#define NH    8
#define NBH   64        // NB*NH
#define NT    4096      // tokens
#define DM    512       // model dim
#define DH    64        // head dim
#define ML    256       // landmarks
#define LG    16        // tokens per landmark group
#define NRT   32768     // NB*NT
#define QN    1536      // 3*NH*DH
#define KSPL  8         // split-K factor for big flash

#define LDS_S 136       // gemm engine A smem row stride
#define BS2   264       // bgemm2 B smem row stride
#define QPAD  136       // flash Q^T staging stride (bank 8kq+r, conflict-free)
#define KPAD  72        // flash K^T / V stride (bank 8kq+cb, conflict-free)
#define PPAD  68        // flash P stride (bank 4r+kq, conflict-free)

// ---------------- scratch (device globals; no allocation allowed) ----------------
__device__ float g_q [NBH * NT * DH];
__device__ float g_k [NBH * NT * DH];
__device__ float g_v [NBH * NT * DH];
__device__ float g_ql[NBH * ML * DH];
__device__ float g_kl[NBH * ML * DH];
__device__ float g_attn2 [NBH * ML * ML];
__device__ unsigned g_scalebits;          // max column-sum as float bits (positive)
__device__ float g_z0[NBH * ML * ML];
__device__ float g_z1[NBH * ML * ML];
__device__ float g_t1[NBH * ML * ML];
__device__ float g_t3[NBH * ML * ML];
__device__ float g_t5[NBH * ML * ML];
__device__ float g_out3[NBH * ML * DH];
__device__ float g_p   [NBH * ML * DH];
__device__ float g_oh  [NRT * DM];
__device__ float g_po[KSPL * NBH * ML * DH];   // split-K partial O (unnormalized)
__device__ float g_pm[KSPL * NBH * ML];        // split-K per-row max
__device__ float g_pl[KSPL * NBH * ML];        // split-K per-row l

__device__ __forceinline__ unsigned f2tf(float f) {
    unsigned r;
    asm("cvt.rna.tf32.f32 %0, %1;" : "=r"(r) : "f"(f));
    return r;
}

__device__ __forceinline__ void mma8(float c[4], const unsigned a[4],
                                     unsigned b0, unsigned b1) {
    asm volatile(
        "mma.sync.aligned.m16n8k8.row.col.f32.tf32.tf32.f32 "
        "{%0,%1,%2,%3}, {%4,%5,%6,%7}, {%8,%9}, {%0,%1,%2,%3};"
        : "+f"(c[0]), "+f"(c[1]), "+f"(c[2]), "+f"(c[3])
        : "r"(a[0]), "r"(a[1]), "r"(a[2]), "r"(a[3]), "r"(b0), "r"(b1));
}

// =====================================================================
// tf32 mma tile engine: 128x128 block tile, BK=16, 256 threads.
// =====================================================================
__device__ __forceinline__ void gemm_tile_tf32(const float* __restrict__ Ag, int lda,
                                               const float* __restrict__ Bg, int ldb,
                                               int K,
                                               unsigned* sA, unsigned* sB,
                                               float acc[4][4][4]) {
    const int tid  = threadIdx.x;
    const int lane = tid & 31;
    const int wid  = tid >> 5;
    const int wr = (wid >> 2) * 64;
    const int wc = (wid & 3) * 32;

    const int a_row = tid & 127;
    const int a_kq  = tid >> 7;
    const int b_kr  = tid >> 5;
    const int b_n4  = tid & 31;

    const int nt = K >> 4;
    float4 ar0, ar1, br0, br1;
    ar0 = *(const float4*)&Ag[(size_t)a_row * lda + a_kq * 4];
    ar1 = *(const float4*)&Ag[(size_t)a_row * lda + (a_kq + 2) * 4];
    br0 = *(const float4*)&Bg[(size_t)b_kr * ldb + b_n4 * 4];
    br1 = *(const float4*)&Bg[(size_t)(b_kr + 8) * ldb + b_n4 * 4];

    {
        unsigned* As = sA;
        unsigned* Bs = sB;
        As[(a_kq * 4 + 0) * LDS_S + a_row] = f2tf(ar0.x);
        As[(a_kq * 4 + 1) * LDS_S + a_row] = f2tf(ar0.y);
        As[(a_kq * 4 + 2) * LDS_S + a_row] = f2tf(ar0.z);
        As[(a_kq * 4 + 3) * LDS_S + a_row] = f2tf(ar0.w);
        As[((a_kq + 2) * 4 + 0) * LDS_S + a_row] = f2tf(ar1.x);
        As[((a_kq + 2) * 4 + 1) * LDS_S + a_row] = f2tf(ar1.y);
        As[((a_kq + 2) * 4 + 2) * LDS_S + a_row] = f2tf(ar1.z);
        As[((a_kq + 2) * 4 + 3) * LDS_S + a_row] = f2tf(ar1.w);
        uint4 b0 = make_uint4(f2tf(br0.x), f2tf(br0.y), f2tf(br0.z), f2tf(br0.w));
        uint4 b1 = make_uint4(f2tf(br1.x), f2tf(br1.y), f2tf(br1.z), f2tf(br1.w));
        *(uint4*)&Bs[b_kr * LDS_S + b_n4 * 4]       = b0;
        *(uint4*)&Bs[(b_kr + 8) * LDS_S + b_n4 * 4] = b1;
    }
    __syncthreads();

    for (int t = 0; t < nt; ++t) {
        unsigned* As = sA + (t & 1) * (16 * LDS_S);
        unsigned* Bs = sB + (t & 1) * (16 * LDS_S);

        if (t + 1 < nt) {
            int k0 = (t + 1) * 16;
            ar0 = *(const float4*)&Ag[(size_t)a_row * lda + k0 + a_kq * 4];
            ar1 = *(const float4*)&Ag[(size_t)a_row * lda + k0 + (a_kq + 2) * 4];
            br0 = *(const float4*)&Bg[(size_t)(k0 + b_kr) * ldb + b_n4 * 4];
            br1 = *(const float4*)&Bg[(size_t)(k0 + b_kr + 8) * ldb + b_n4 * 4];
        }

#pragma unroll
        for (int kk = 0; kk < 16; kk += 8) {
            unsigned a[4][4], b[4][2];
            const int kr0 = kk + (lane & 3);
            const int kr1 = kk + (lane & 3) + 4;
#pragma unroll
            for (int ma = 0; ma < 4; ++ma) {
                int r = wr + ma * 16 + (lane >> 2);
                a[ma][0] = As[kr0 * LDS_S + r];
                a[ma][1] = As[kr0 * LDS_S + r + 8];
                a[ma][2] = As[kr1 * LDS_S + r];
                a[ma][3] = As[kr1 * LDS_S + r + 8];
            }
#pragma unroll
            for (int na = 0; na < 4; ++na) {
                int c = wc + na * 8 + (lane >> 2);
                b[na][0] = Bs[kr0 * LDS_S + c];
                b[na][1] = Bs[kr1 * LDS_S + c];
            }
#pragma unroll
            for (int ma = 0; ma < 4; ++ma)
#pragma unroll
                for (int na = 0; na < 4; ++na)
                    mma8(acc[ma][na], a[ma], b[na][0], b[na][1]);
        }

        if (t + 1 < nt) {
            unsigned* An = sA + ((t + 1) & 1) * (16 * LDS_S);
            unsigned* Bn = sB + ((t + 1) & 1) * (16 * LDS_S);
            An[(a_kq * 4 + 0) * LDS_S + a_row] = f2tf(ar0.x);
            An[(a_kq * 4 + 1) * LDS_S + a_row] = f2tf(ar0.y);
            An[(a_kq * 4 + 2) * LDS_S + a_row] = f2tf(ar0.z);
            An[(a_kq * 4 + 3) * LDS_S + a_row] = f2tf(ar0.w);
            An[((a_kq + 2) * 4 + 0) * LDS_S + a_row] = f2tf(ar1.x);
            An[((a_kq + 2) * 4 + 1) * LDS_S + a_row] = f2tf(ar1.y);
            An[((a_kq + 2) * 4 + 2) * LDS_S + a_row] = f2tf(ar1.z);
            An[((a_kq + 2) * 4 + 3) * LDS_S + a_row] = f2tf(ar1.w);
            uint4 b0 = make_uint4(f2tf(br0.x), f2tf(br0.y), f2tf(br0.z), f2tf(br0.w));
            uint4 b1 = make_uint4(f2tf(br1.x), f2tf(br1.y), f2tf(br1.z), f2tf(br1.w));
            *(uint4*)&Bn[b_kr * LDS_S + b_n4 * 4]       = b0;
            *(uint4*)&Bn[(b_kr + 8) * LDS_S + b_n4 * 4] = b1;
        }
        __syncthreads();
    }
}

// =====================================================================
// Kernel 1: qkv = x @ w_qkv, scatter to q/k/v head-major, scale q.
// =====================================================================
__global__ void __launch_bounds__(256) k_qkv(const float* __restrict__ X,
                                             const float* __restrict__ W) {
    __shared__ unsigned sA[2 * 16 * LDS_S];
    __shared__ unsigned sB[2 * 16 * LDS_S];
    const int colbase = blockIdx.x * 128;
    const int rowbase = blockIdx.y * 128;
    float acc[4][4][4];
#pragma unroll
    for (int i = 0; i < 4; ++i)
#pragma unroll
        for (int j = 0; j < 4; ++j)
#pragma unroll
            for (int u = 0; u < 4; ++u) acc[i][j][u] = 0.f;

    gemm_tile_tf32(X + (size_t)rowbase * DM, DM, W + colbase, QN, DM, sA, sB, acc);

    const int lane = threadIdx.x & 31, wid = threadIdx.x >> 5;
    const int wr = (wid >> 2) * 64, wc = (wid & 3) * 32;
#pragma unroll
    for (int ma = 0; ma < 4; ++ma) {
#pragma unroll
        for (int na = 0; na < 4; ++na) {
            int r0 = rowbase + wr + ma * 16 + (lane >> 2);
            int c  = colbase + wc + na * 8 + (lane & 3) * 2;
            int part = c >> 9, rem = c & 511;
            int h = rem >> 6, d = rem & 63;
#pragma unroll
            for (int half = 0; half < 2; ++half) {
                int r = r0 + half * 8;
                int bb = r >> 12, n = r & 4095;
                size_t dst = (((size_t)(bb * 8 + h)) * NT + n) * DH + d;
                float v0 = acc[ma][na][half * 2 + 0];
                float v1 = acc[ma][na][half * 2 + 1];
                if (part == 0)      *(float2*)&g_q[dst] = make_float2(v0 * 0.125f, v1 * 0.125f);
                else if (part == 1) *(float2*)&g_k[dst] = make_float2(v0, v1);
                else                *(float2*)&g_v[dst] = make_float2(v0, v1);
            }
        }
    }
}

// =====================================================================
// Kernel 7: batched GEMM for pinv, 128x256 CTA tile, grid (NBH, 2).
// =====================================================================
__global__ void __launch_bounds__(256) k_bgemm2(const float* __restrict__ A,
                                                const float* __restrict__ B,
                                                const float* __restrict__ E,
                                                float* __restrict__ C,
                                                float alpha, float beta) {
    extern __shared__ unsigned dsm[];
    unsigned* sA = dsm;
    unsigned* sB = dsm + 2 * 16 * LDS_S;
    const int tid = threadIdx.x;
    const int lane = tid & 31, w = tid >> 5;
    const int wr = (w >> 2) * 64;
    const int wc = (w & 3) * 64;
    const size_t base = (size_t)blockIdx.x * (ML * ML);
    const int rowbase = blockIdx.y * 128;
    const float* Ag = A + base + (size_t)rowbase * ML;
    const float* Bg = B + base;

    const int a_row = tid & 127;
    const int a_kq  = tid >> 7;
    const int b_kr  = tid >> 4;
    const int b_c0  = (tid & 15) * 16;

    float acc[4][8][4];
#pragma unroll
    for (int i = 0; i < 4; ++i)
#pragma unroll
        for (int j = 0; j < 8; ++j)
#pragma unroll
            for (int u = 0; u < 4; ++u) acc[i][j][u] = 0.f;

    float4 ar0, ar1, bv[4];
    ar0 = *(const float4*)&Ag[(size_t)a_row * ML + a_kq * 4];
    ar1 = *(const float4*)&Ag[(size_t)a_row * ML + (a_kq + 2) * 4];
#pragma unroll
    for (int i = 0; i < 4; ++i)
        bv[i] = *(const float4*)&Bg[(size_t)b_kr * ML + b_c0 + 4 * i];

    {
        unsigned* As = sA;
        unsigned* Bs = sB;
        As[(a_kq * 4 + 0) * LDS_S + a_row] = f2tf(ar0.x);
        As[(a_kq * 4 + 1) * LDS_S + a_row] = f2tf(ar0.y);
        As[(a_kq * 4 + 2) * LDS_S + a_row] = f2tf(ar0.z);
        As[(a_kq * 4 + 3) * LDS_S + a_row] = f2tf(ar0.w);
        As[((a_kq + 2) * 4 + 0) * LDS_S + a_row] = f2tf(ar1.x);
        As[((a_kq + 2) * 4 + 1) * LDS_S + a_row] = f2tf(ar1.y);
        As[((a_kq + 2) * 4 + 2) * LDS_S + a_row] = f2tf(ar1.z);
        As[((a_kq + 2) * 4 + 3) * LDS_S + a_row] = f2tf(ar1.w);
#pragma unroll
        for (int i = 0; i < 4; ++i) {
            uint4 bt = make_uint4(f2tf(bv[i].x), f2tf(bv[i].y), f2tf(bv[i].z), f2tf(bv[i].w));
            *(uint4*)&Bs[b_kr * BS2 + b_c0 + 4 * i] = bt;
        }
    }
    __syncthreads();

    for (int t = 0; t < 16; ++t) {
        unsigned* As = sA + (t & 1) * (16 * LDS_S);
        unsigned* Bs = sB + (t & 1) * (16 * BS2);

        if (t + 1 < 16) {
            int k0 = (t + 1) * 16;
            ar0 = *(const float4*)&Ag[(size_t)a_row * ML + k0 + a_kq * 4];
            ar1 = *(const float4*)&Ag[(size_t)a_row * ML + k0 + (a_kq + 2) * 4];
#pragma unroll
            for (int i = 0; i < 4; ++i)
                bv[i] = *(const float4*)&Bg[(size_t)(k0 + b_kr) * ML + b_c0 + 4 * i];
        }

#pragma unroll
        for (int kk = 0; kk < 16; kk += 8) {
            unsigned a[4][4], b[8][2];
            const int kr0 = kk + (lane & 3);
            const int kr1 = kk + (lane & 3) + 4;
#pragma unroll
            for (int ma = 0; ma < 4; ++ma) {
                int r = wr + ma * 16 + (lane >> 2);
                a[ma][0] = As[kr0 * LDS_S + r];
                a[ma][1] = As[kr0 * LDS_S + r + 8];
                a[ma][2] = As[kr1 * LDS_S + r];
                a[ma][3] = As[kr1 * LDS_S + r + 8];
            }
#pragma unroll
            for (int na = 0; na < 8; ++na) {
                int c = wc + na * 8 + (lane >> 2);
                b[na][0] = Bs[kr0 * BS2 + c];
                b[na][1] = Bs[kr1 * BS2 + c];
            }
#pragma unroll
            for (int ma = 0; ma < 4; ++ma)
#pragma unroll
                for (int na = 0; na < 8; ++na)
                    mma8(acc[ma][na], a[ma], b[na][0], b[na][1]);
        }

        if (t + 1 < 16) {
            unsigned* An = sA + ((t + 1) & 1) * (16 * LDS_S);
            unsigned* Bn = sB + ((t + 1) & 1) * (16 * BS2);
            An[(a_kq * 4 + 0) * LDS_S + a_row] = f2tf(ar0.x);
            An[(a_kq * 4 + 1) * LDS_S + a_row] = f2tf(ar0.y);
            An[(a_kq * 4 + 2) * LDS_S + a_row] = f2tf(ar0.z);
            An[(a_kq * 4 + 3) * LDS_S + a_row] = f2tf(ar0.w);
            An[((a_kq + 2) * 4 + 0) * LDS_S + a_row] = f2tf(ar1.x);
            An[((a_kq + 2) * 4 + 1) * LDS_S + a_row] = f2tf(ar1.y);
            An[((a_kq + 2) * 4 + 2) * LDS_S + a_row] = f2tf(ar1.z);
            An[((a_kq + 2) * 4 + 3) * LDS_S + a_row] = f2tf(ar1.w);
#pragma unroll
            for (int i = 0; i < 4; ++i) {
                uint4 bt = make_uint4(f2tf(bv[i].x), f2tf(bv[i].y), f2tf(bv[i].z), f2tf(bv[i].w));
                *(uint4*)&Bn[b_kr * BS2 + b_c0 + 4 * i] = bt;
            }
        }
        __syncthreads();
    }

#pragma unroll
    for (int ma = 0; ma < 4; ++ma) {
#pragma unroll
        for (int na = 0; na < 8; ++na) {
            int r0 = rowbase + wr + ma * 16 + (lane >> 2);
            int c  = wc + na * 8 + (lane & 3) * 2;
            size_t i0 = base + (size_t)r0 * ML + c;
            size_t i1 = i0 + 8 * ML;
            float2 e0 = make_float2(0.f, 0.f), e1 = make_float2(0.f, 0.f);
            if (beta != 0.f) { e0 = *(const float2*)&E[i0]; e1 = *(const float2*)&E[i1]; }
            float2 o0 = make_float2(alpha * acc[ma][na][0] + beta * e0.x,
                                    alpha * acc[ma][na][1] + beta * e0.y);
            float2 o1 = make_float2(alpha * acc[ma][na][2] + beta * e1.x,
                                    alpha * acc[ma][na][3] + beta * e1.y);
            *(float2*)&C[i0] = o0;
            *(float2*)&C[i1] = o1;
        }
    }
}

// =====================================================================
// Kernel 10: Y = oh @ w_out + b_out
// =====================================================================
__global__ void __launch_bounds__(256) k_final(const float* __restrict__ W,
                                               const float* __restrict__ bias,
                                               float* __restrict__ Y) {
    __shared__ unsigned sA[2 * 16 * LDS_S];
    __shared__ unsigned sB[2 * 16 * LDS_S];
    const int colbase = blockIdx.x * 128;
    const int rowbase = blockIdx.y * 128;
    float acc[4][4][4];
#pragma unroll
    for (int i = 0; i < 4; ++i)
#pragma unroll
        for (int j = 0; j < 4; ++j)
#pragma unroll
            for (int u = 0; u < 4; ++u) acc[i][j][u] = 0.f;

    gemm_tile_tf32(g_oh + (size_t)rowbase * DM, DM, W + colbase, DM, DM, sA, sB, acc);

    const int lane = threadIdx.x & 31, wid = threadIdx.x >> 5;
    const int wr = (wid >> 2) * 64, wc = (wid & 3) * 32;
#pragma unroll
    for (int ma = 0; ma < 4; ++ma) {
#pragma unroll
        for (int na = 0; na < 4; ++na) {
            int r0 = rowbase + wr + ma * 16 + (lane >> 2);
            int c  = colbase + wc + na * 8 + (lane & 3) * 2;
            float2 bb = *(const float2*)&bias[c];
            float2 o0 = make_float2(acc[ma][na][0] + bb.x, acc[ma][na][1] + bb.y);
            float2 o1 = make_float2(acc[ma][na][2] + bb.x, acc[ma][na][3] + bb.y);
            *(float2*)&Y[(size_t)r0 * DM + c] = o0;
            *(float2*)&Y[(size_t)(r0 + 8) * DM + c] = o1;
        }
    }
}

// =====================================================================
// Kernel 2: landmarks = mean over groups of 16 tokens.
// =====================================================================
__global__ void k_landmark() {
    const int blk = blockIdx.x;
    const int bh = blk >> 8, m = blk & 255;
    const int d = threadIdx.x;
    const float* qb = g_q + ((size_t)bh * NT + m * LG) * DH + d;
    const float* kb = g_k + ((size_t)bh * NT + m * LG) * DH + d;
    float sq = 0.f, sk = 0.f;
#pragma unroll
    for (int t = 0; t < LG; ++t) { sq += qb[t * DH]; sk += kb[t * DH]; }
    g_ql[((size_t)bh * ML + m) * DH + d] = sq * (1.f / LG);
    g_kl[((size_t)bh * ML + m) * DH + d] = sk * (1.f / LG);
}

// =====================================================================
// Kernel 3: attn2 = softmax(ql @ kl^T) rows. Also resets g_scalebits.
// =====================================================================
__global__ void __launch_bounds__(256) k_attn2() {
    extern __shared__ float sm[];
    float* qls   = sm;
    float* kls   = sm + 64 * 68;
    float* sc    = kls + 256 * 68;
    float* rowiv = sc + 64 * 256;
    const int bh = blockIdx.x, chunk = blockIdx.y, tid = threadIdx.x;

    if (bh == 0 && chunk == 0 && tid == 0) g_scalebits = 0u;

    const float* klb = g_kl + (size_t)bh * ML * DH;
    for (int i = tid; i < 256 * 16; i += 256) {
        int row = i >> 4, c4 = (i & 15) * 4;
        *(float4*)&kls[row * 68 + c4] = *(const float4*)&klb[row * DH + c4];
    }
    const float* qlb = g_ql + ((size_t)bh * ML + chunk * 64) * DH;
    for (int i = tid; i < 64 * 16; i += 256) {
        int row = i >> 4, c4 = (i & 15) * 4;
        *(float4*)&qls[row * 68 + c4] = *(const float4*)&qlb[row * DH + c4];
    }
    __syncthreads();

    const int r = tid >> 2, cg = tid & 3;
    float4 qreg[16];
#pragma unroll
    for (int u = 0; u < 16; ++u) qreg[u] = *(const float4*)&qls[r * 68 + u * 4];

    float mloc = -1e30f;
    for (int ci = 0; ci < 64; ++ci) {
        int c = ci * 4 + cg;
        const float4* kv = (const float4*)&kls[c * 68];
        float s = 0.f;
#pragma unroll
        for (int u = 0; u < 16; ++u) {
            float4 k4 = kv[u];
            s += qreg[u].x * k4.x + qreg[u].y * k4.y + qreg[u].z * k4.z + qreg[u].w * k4.w;
        }
        sc[r * 256 + c] = s;
        mloc = fmaxf(mloc, s);
    }
    mloc = fmaxf(mloc, __shfl_xor_sync(0xFFFFFFFFu, mloc, 1));
    mloc = fmaxf(mloc, __shfl_xor_sync(0xFFFFFFFFu, mloc, 2));
    float ssum = 0.f;
    for (int ci = 0; ci < 64; ++ci) {
        int c = ci * 4 + cg;
        float p = __expf(sc[r * 256 + c] - mloc);
        sc[r * 256 + c] = p;
        ssum += p;
    }
    ssum += __shfl_xor_sync(0xFFFFFFFFu, ssum, 1);
    ssum += __shfl_xor_sync(0xFFFFFFFFu, ssum, 2);
    if (cg == 0) rowiv[r] = 1.f / ssum;
    __syncthreads();

    float* dst = g_attn2 + (size_t)bh * (ML * ML) + (size_t)chunk * 64 * 256;
    for (int i = tid; i < 64 * 256; i += 256)
        dst[i] = sc[i] * rowiv[i >> 8];
}

// =====================================================================
// Kernel 4: column sums + fused global max.
// =====================================================================
__global__ void k_colsum() {
    __shared__ float red[256];
    const int bh = blockIdx.x, j = threadIdx.x;
    const float* a = g_attn2 + (size_t)bh * (ML * ML);
    float s = 0.f;
    for (int i = 0; i < ML; ++i) s += a[i * ML + j];
    red[j] = s;
    __syncthreads();
    for (int st = 128; st > 0; st >>= 1) {
        if (j < st) red[j] = fmaxf(red[j], red[j + st]);
        __syncthreads();
    }
    if (j == 0) atomicMax(&g_scalebits, __float_as_uint(red[0]));
}

__global__ void k_zinit() {
    const int bh = blockIdx.x;
    const float scl = 1.f / __uint_as_float(g_scalebits);
    float* z = g_z0 + (size_t)bh * (ML * ML);
    const float* a = g_attn2 + (size_t)bh * (ML * ML);
    for (int idx = threadIdx.x; idx < ML * ML; idx += 256) {
        int i = idx >> 8, j = idx & 255;
        z[idx] = a[j * ML + i] * scl;
    }
}

// =====================================================================
// Flash core v2: 128 q rows/CTA, 8 warps x (16 rows x 64 keys),
// register online softmax (full key row per lane-quad),
// conflict-free smem strides, P through smem once (tf32).
// =====================================================================
template<int PART>
__device__ __forceinline__ void flash_body(const float* __restrict__ Q,
                                           const float* __restrict__ K,
                                           const float* __restrict__ V,
                                           float* __restrict__ Out,
                                           int nkeys_total, int ntiles, int ktile0,
                                           int mode) {
    extern __shared__ unsigned usm[];
    unsigned* QT = usm;                         // [64][QPAD] Q^T staging (dead after qf)
    unsigned* PS = usm;                         // [128][PPAD] P tile (reuses QT: both 8704 words)
    unsigned* KT = usm + 64 * QPAD;             // [64][KPAD] K^T
    unsigned* VS = KT + 64 * KPAD;              // [64][KPAD] V

    const int tid = threadIdx.x;
    const int lane = tid & 31, w = tid >> 5;
    const int wrow = w * 16;
    const int bh = blockIdx.x, chunk = blockIdx.y;
    const int nq = (int)gridDim.y * 128;

    const float* Qb = Q + ((size_t)bh * nq + chunk * 128) * DH;
    const float* Kb = K + (size_t)bh * nkeys_total * DH;
    const float* Vb = V + (size_t)bh * nkeys_total * DH;

    // stage Q^T [dh][qrow] tf32
    {
        const int qrow = tid & 127;
        const int qc0 = (tid >> 7) * 32;
#pragma unroll
        for (int i = 0; i < 8; ++i) {
            float4 qv = *(const float4*)&Qb[qrow * DH + qc0 + 4 * i];
            QT[(qc0 + 4*i + 0) * QPAD + qrow] = f2tf(qv.x);
            QT[(qc0 + 4*i + 1) * QPAD + qrow] = f2tf(qv.y);
            QT[(qc0 + 4*i + 2) * QPAD + qrow] = f2tf(qv.z);
            QT[(qc0 + 4*i + 3) * QPAD + qrow] = f2tf(qv.w);
        }
    }
    __syncthreads();

    const int r  = wrow + (lane >> 2);
    const int kq = lane & 3;
    const int cb = lane >> 2;
    unsigned qf[8][4];
#pragma unroll
    for (int ka = 0; ka < 8; ++ka) {
        qf[ka][0] = QT[(8*ka + kq) * QPAD + r];
        qf[ka][1] = QT[(8*ka + kq) * QPAD + r + 8];
        qf[ka][2] = QT[(8*ka + kq + 4) * QPAD + r];
        qf[ka][3] = QT[(8*ka + kq + 4) * QPAD + r + 8];
    }
    __syncthreads();   // QT dead; PS region free

    float oacc[8][4];
#pragma unroll
    for (int na = 0; na < 8; ++na)
#pragma unroll
        for (int u = 0; u < 4; ++u) oacc[na][u] = 0.f;
    float m0 = -1e30f, m1 = -1e30f, l0 = 0.f, l1 = 0.f;

    const int strow = tid & 63;
    const int stc0  = (tid >> 6) * 16;

    for (int kt = ktile0; kt < ktile0 + ntiles; ++kt) {
        // stage K^T and V (tf32)
        {
            const float* Kt_ = Kb + (size_t)kt * 64 * DH;
            const float* Vt_ = Vb + (size_t)kt * 64 * DH;
#pragma unroll
            for (int i = 0; i < 4; ++i) {
                float4 kv = *(const float4*)&Kt_[strow * DH + stc0 + 4 * i];
                KT[(stc0 + 4*i + 0) * KPAD + strow] = f2tf(kv.x);
                KT[(stc0 + 4*i + 1) * KPAD + strow] = f2tf(kv.y);
                KT[(stc0 + 4*i + 2) * KPAD + strow] = f2tf(kv.z);
                KT[(stc0 + 4*i + 3) * KPAD + strow] = f2tf(kv.w);
                float4 vv = *(const float4*)&Vt_[strow * DH + stc0 + 4 * i];
                uint4 vt = make_uint4(f2tf(vv.x), f2tf(vv.y), f2tf(vv.z), f2tf(vv.w));
                *(uint4*)&VS[strow * KPAD + stc0 + 4 * i] = vt;
            }
        }
        __syncthreads();

        // S = Q @ K^T  (warp covers full 64-key width)
        float sacc[8][4];
#pragma unroll
        for (int na = 0; na < 8; ++na)
#pragma unroll
            for (int u = 0; u < 4; ++u) sacc[na][u] = 0.f;
#pragma unroll
        for (int ka = 0; ka < 8; ++ka) {
#pragma unroll
            for (int na = 0; na < 8; ++na) {
                unsigned b0 = KT[(8*ka + kq) * KPAD + 8*na + cb];
                unsigned b1 = KT[(8*ka + kq + 4) * KPAD + 8*na + cb];
                mma8(sacc[na], qf[ka], b0, b1);
            }
        }

        // register online softmax: rows r (sacc[.][0..1]) and r+8 (sacc[.][2..3])
        {
            float t0 = -1e30f, t1 = -1e30f;
#pragma unroll
            for (int na = 0; na < 8; ++na) {
                t0 = fmaxf(t0, fmaxf(sacc[na][0], sacc[na][1]));
                t1 = fmaxf(t1, fmaxf(sacc[na][2], sacc[na][3]));
            }
            t0 = fmaxf(t0, __shfl_xor_sync(0xFFFFFFFFu, t0, 1));
            t0 = fmaxf(t0, __shfl_xor_sync(0xFFFFFFFFu, t0, 2));
            t1 = fmaxf(t1, __shfl_xor_sync(0xFFFFFFFFu, t1, 1));
            t1 = fmaxf(t1, __shfl_xor_sync(0xFFFFFFFFu, t1, 2));
            float mn0 = fmaxf(m0, t0), mn1 = fmaxf(m1, t1);
            float f0 = __expf(m0 - mn0), f1 = __expf(m1 - mn1);
            float ps0 = 0.f, ps1 = 0.f;
#pragma unroll
            for (int na = 0; na < 8; ++na) {
                float p00 = __expf(sacc[na][0] - mn0);
                float p01 = __expf(sacc[na][1] - mn0);
                float p10 = __expf(sacc[na][2] - mn1);
                float p11 = __expf(sacc[na][3] - mn1);
                ps0 += p00 + p01;
                ps1 += p10 + p11;
                *(uint2*)&PS[r * PPAD + 8*na + 2*kq]       = make_uint2(f2tf(p00), f2tf(p01));
                *(uint2*)&PS[(r + 8) * PPAD + 8*na + 2*kq] = make_uint2(f2tf(p10), f2tf(p11));
            }
            ps0 += __shfl_xor_sync(0xFFFFFFFFu, ps0, 1);
            ps0 += __shfl_xor_sync(0xFFFFFFFFu, ps0, 2);
            ps1 += __shfl_xor_sync(0xFFFFFFFFu, ps1, 1);
            ps1 += __shfl_xor_sync(0xFFFFFFFFu, ps1, 2);
            l0 = l0 * f0 + ps0; m0 = mn0;
            l1 = l1 * f1 + ps1; m1 = mn1;
#pragma unroll
            for (int na = 0; na < 8; ++na) {
                oacc[na][0] *= f0; oacc[na][1] *= f0;
                oacc[na][2] *= f1; oacc[na][3] *= f1;
            }
        }
        __syncwarp();   // P rows for this warp written only by this warp

        // O += P @ V
#pragma unroll
        for (int ka = 0; ka < 8; ++ka) {
            unsigned a[4];
            a[0] = PS[r * PPAD + 8*ka + kq];
            a[1] = PS[(r + 8) * PPAD + 8*ka + kq];
            a[2] = PS[r * PPAD + 8*ka + kq + 4];
            a[3] = PS[(r + 8) * PPAD + 8*ka + kq + 4];
#pragma unroll
            for (int na = 0; na < 8; ++na) {
                unsigned b0 = VS[(8*ka + kq) * KPAD + 8*na + cb];
                unsigned b1 = VS[(8*ka + kq + 4) * KPAD + 8*na + cb];
                mma8(oacc[na], a, b0, b1);
            }
        }
        __syncthreads();   // before next stage overwrites KT/VS
    }

    const int g0 = chunk * 128 + r;
    if (PART) {
        const int s = blockIdx.z;
        float* po = g_po + ((size_t)(s * NBH + bh) * ML) * DH;
#pragma unroll
        for (int na = 0; na < 8; ++na) {
            *(float2*)&po[(size_t)g0 * DH + 8*na + 2*kq] =
                make_float2(oacc[na][0], oacc[na][1]);
            *(float2*)&po[(size_t)(g0 + 8) * DH + 8*na + 2*kq] =
                make_float2(oacc[na][2], oacc[na][3]);
        }
        if (kq == 0) {
            size_t mi = (size_t)(s * NBH + bh) * ML;
            g_pm[mi + g0] = m0;     g_pl[mi + g0] = l0;
            g_pm[mi + g0 + 8] = m1; g_pl[mi + g0 + 8] = l1;
        }
    } else {
        const float i0 = 1.f / l0, i1 = 1.f / l1;
        size_t obase; int ostride;
        if (mode == 0) { obase = (size_t)bh * nq * DH; ostride = DH; }
        else {
            int b_ = bh >> 3, h = bh & 7;
            obase = (size_t)b_ * NT * DM + h * DH;
            ostride = DM;
        }
#pragma unroll
        for (int na = 0; na < 8; ++na) {
            *(float2*)&Out[obase + (size_t)g0 * ostride + 8*na + 2*kq] =
                make_float2(oacc[na][0] * i0, oacc[na][1] * i0);
            *(float2*)&Out[obase + (size_t)(g0 + 8) * ostride + 8*na + 2*kq] =
                make_float2(oacc[na][2] * i1, oacc[na][3] * i1);
        }
    }
}

__global__ void __launch_bounds__(256) k_flash(const float* __restrict__ Q,
                                               const float* __restrict__ K,
                                               const float* __restrict__ V,
                                               float* __restrict__ Out,
                                               int nkeys, int mode) {
    flash_body<0>(Q, K, V, Out, nkeys, nkeys >> 6, 0, mode);
}

// split-K partial flash: grid (NBH, 2, KSPL), 512 keys per split, 128 q rows/CTA
__global__ void __launch_bounds__(256) k_flash_part(const float* __restrict__ Q,
                                                    const float* __restrict__ K,
                                                    const float* __restrict__ V) {
    const int s = blockIdx.z;
    flash_body<1>(Q, K, V, nullptr, NT, (NT / KSPL) >> 6, s * ((NT / KSPL) >> 6), 0);
}

// combine: out3 = sum_s po_s * exp(m_s - gm) / sum_s l_s * exp(m_s - gm)
__global__ void __launch_bounds__(256) k_combine() {
    const int bh = blockIdx.x, chunk = blockIdx.y, tid = threadIdx.x;
    const int q = chunk * 64 + (tid >> 2);
    const int d0 = (tid & 3) * 16;

    float m[KSPL], l[KSPL];
    float gm = -1e30f;
#pragma unroll
    for (int s = 0; s < KSPL; ++s) {
        size_t mi = (size_t)(s * NBH + bh) * ML + q;
        m[s] = g_pm[mi];
        l[s] = g_pl[mi];
        gm = fmaxf(gm, m[s]);
    }
    float L = 0.f;
    float wgt[KSPL];
#pragma unroll
    for (int s = 0; s < KSPL; ++s) {
        wgt[s] = __expf(m[s] - gm);
        L += l[s] * wgt[s];
    }
    float4 o[4];
#pragma unroll
    for (int u = 0; u < 4; ++u) o[u] = make_float4(0.f, 0.f, 0.f, 0.f);
#pragma unroll
    for (int s = 0; s < KSPL; ++s) {
        const float* po = g_po + (((size_t)(s * NBH + bh) * ML + q)) * DH + d0;
        float ws = wgt[s];
#pragma unroll
        for (int u = 0; u < 4; ++u) {
            float4 pv = *(const float4*)&po[u * 4];
            o[u].x = fmaf(ws, pv.x, o[u].x);
            o[u].y = fmaf(ws, pv.y, o[u].y);
            o[u].z = fmaf(ws, pv.z, o[u].z);
            o[u].w = fmaf(ws, pv.w, o[u].w);
        }
    }
    float inv = 1.f / L;
    float* dst = g_out3 + ((size_t)bh * ML + q) * DH + d0;
#pragma unroll
    for (int u = 0; u < 4; ++u) {
        *(float4*)&dst[u * 4] = make_float4(o[u].x * inv, o[u].y * inv,
                                            o[u].z * inv, o[u].w * inv);
    }
}

// =====================================================================
// Kernel 9: p = z @ out3  ([256,256]@[256,64] per bh)
// =====================================================================
__global__ void __launch_bounds__(256) k_pmat(const float* __restrict__ Z) {
    extern __shared__ float sm[];
    const int bh = blockIdx.x, tid = threadIdx.x;
    const float* o3 = g_out3 + (size_t)bh * ML * DH;
    for (int i = tid; i < ML * 16; i += 256)
        ((float4*)sm)[i] = ((const float4*)o3)[i];
    __syncthreads();

    const float* zrow = Z + ((size_t)bh * ML + tid) * ML;
    float4 acc[16];
#pragma unroll
    for (int u = 0; u < 16; ++u) acc[u] = make_float4(0.f, 0.f, 0.f, 0.f);
    for (int j = 0; j < ML; ++j) {
        float zij = zrow[j];
        const float4* vr = (const float4*)&sm[j * DH];
#pragma unroll
        for (int u = 0; u < 16; ++u) {
            float4 v = vr[u];
            acc[u].x = fmaf(zij, v.x, acc[u].x);
            acc[u].y = fmaf(zij, v.y, acc[u].y);
            acc[u].z = fmaf(zij, v.z, acc[u].z);
            acc[u].w = fmaf(zij, v.w, acc[u].w);
        }
    }
    float4* dst = (float4*)(g_p + ((size_t)bh * ML + tid) * DH);
#pragma unroll
    for (int u = 0; u < 16; ++u) dst[u] = acc[u];
}

// =====================================================================
// Host launcher
// =====================================================================
extern "C" void kernel_launch(void* const* d_in, const int* in_sizes, int n_in,
                              void* d_out, int out_size) {
    (void)in_sizes; (void)n_in; (void)out_size;
    const float* x     = (const float*)d_in[0];
    const float* w_qkv = (const float*)d_in[1];
    const float* w_out = (const float*)d_in[2];
    const float* b_out = (const float*)d_in[3];
    float* out = (float*)d_out;

    const int FLASH_SMEM = (64 * QPAD + 2 * 64 * KPAD) * 4;       // 71680
    const int ATTN2_SMEM = (64*68 + 256*68 + 64*256 + 64) * 4;
    const int PMAT_SMEM  = ML * DH * 4;
    const int BG2_SMEM   = (2 * 16 * LDS_S + 2 * 16 * BS2) * 4;
    cudaFuncSetAttribute(k_flash, cudaFuncAttributeMaxDynamicSharedMemorySize, FLASH_SMEM);
    cudaFuncSetAttribute(k_flash_part, cudaFuncAttributeMaxDynamicSharedMemorySize, FLASH_SMEM);
    cudaFuncSetAttribute(k_attn2, cudaFuncAttributeMaxDynamicSharedMemorySize, ATTN2_SMEM);
    cudaFuncSetAttribute(k_pmat,  cudaFuncAttributeMaxDynamicSharedMemorySize, PMAT_SMEM);
    cudaFuncSetAttribute(k_bgemm2, cudaFuncAttributeMaxDynamicSharedMemorySize, BG2_SMEM);

    float *z0, *z1, *t1, *t3, *t5, *a2, *ql, *kl, *kp, *vp, *qp, *pp, *oh;
    cudaGetSymbolAddress((void**)&z0, g_z0);
    cudaGetSymbolAddress((void**)&z1, g_z1);
    cudaGetSymbolAddress((void**)&t1, g_t1);
    cudaGetSymbolAddress((void**)&t3, g_t3);
    cudaGetSymbolAddress((void**)&t5, g_t5);
    cudaGetSymbolAddress((void**)&a2, g_attn2);
    cudaGetSymbolAddress((void**)&ql, g_ql);
    cudaGetSymbolAddress((void**)&kl, g_kl);
    cudaGetSymbolAddress((void**)&kp, g_k);
    cudaGetSymbolAddress((void**)&vp, g_v);
    cudaGetSymbolAddress((void**)&qp, g_q);
    cudaGetSymbolAddress((void**)&pp, g_p);
    cudaGetSymbolAddress((void**)&oh, g_oh);

    // 1. projections + head scatter (tf32 mma)
    k_qkv<<<dim3(12, 256), 256>>>(x, w_qkv);
    // 2. landmarks
    k_landmark<<<NBH * ML, DH>>>();
    // 3. attn2 (softmaxed); resets g_scalebits
    k_attn2<<<dim3(NBH, 4), 256, ATTN2_SMEM>>>();
    // 4. out3 partials = flash(ql, k, v) over 4096 keys, split-K x8 (128 q rows/CTA)
    k_flash_part<<<dim3(NBH, 2, KSPL), 256, FLASH_SMEM>>>(ql, kp, vp);
    k_combine<<<dim3(NBH, 4), 256>>>();
    // 5. pinv init: colsum/max + z0
    k_colsum<<<NBH, ML>>>();
    k_zinit<<<NBH, 256>>>();
    // 6. Moore-Penrose iterations (wide-tile GEMMs)
    float* zc = z0; float* zn = z1;
    for (int it = 0; it < 6; ++it) {
        k_bgemm2<<<dim3(NBH, 2), 256, BG2_SMEM>>>(a2, zc, a2, t1,  1.f,   0.f);
        k_bgemm2<<<dim3(NBH, 2), 256, BG2_SMEM>>>(t1, t1, t1, t3, -1.f,   7.f);
        k_bgemm2<<<dim3(NBH, 2), 256, BG2_SMEM>>>(t1, t3, t1, t5, -1.f,  15.f);
        k_bgemm2<<<dim3(NBH, 2), 256, BG2_SMEM>>>(zc, t5, zc, zn, -0.25f, 3.25f);
        float* tmp = zc; zc = zn; zn = tmp;
    }
    // 7. p = attn2_inv @ out3
    k_pmat<<<NBH, 256, PMAT_SMEM>>>(zc);
    // 8. oh = softmax(q@kl^T) @ p  (flash over 256 keys, 128 q rows/CTA)
    k_flash<<<dim3(NBH, 32), 256, FLASH_SMEM>>>(qp, kl, pp, oh, ML, 1);
    // 9. final projection + bias (tf32 mma)
    k_final<<<dim3(4, 256), 256>>>(w_out, b_out, out);
}